// round 2
// baseline (speedup 1.0000x reference)
#include <cuda_runtime.h>
#include <cstdint>
#include <math.h>

#define D_DIM   1024
#define N_BATCH 8
#define N_SEQ   4096
#define M_FLAT  (N_BATCH * N_SEQ)   // 32768

// ---------------- scratch (device globals: no allocation allowed) ----------
__device__ float g_Q [(size_t)M_FLAT * D_DIM];            // 134 MB
__device__ float g_Kf[(size_t)M_FLAT * D_DIM];            // 134 MB (feature-mapped K)
__device__ float g_V [(size_t)M_FLAT * D_DIM];            // 134 MB
__device__ float g_Cx[(size_t)M_FLAT * D_DIM];            // 134 MB (context)
__device__ float g_KV[(size_t)N_BATCH * D_DIM * D_DIM];   // 33.5 MB
__device__ float g_Ksum[N_BATCH * D_DIM];
__device__ float g_Z[M_FLAT];

// ---------------- helpers ----------------
__device__ __forceinline__ uint32_t f2tf32(float f) {
    uint32_t u;
    asm("cvt.rna.tf32.f32 %0, %1;" : "=r"(u) : "f"(f));
    return u;
}

__device__ __forceinline__ void mma8(float c[4], const uint32_t a[4], const uint32_t b[2]) {
    asm volatile(
        "mma.sync.aligned.m16n8k8.row.col.f32.tf32.tf32.f32 "
        "{%0,%1,%2,%3}, {%4,%5,%6,%7}, {%8,%9}, {%0,%1,%2,%3};\n"
        : "+f"(c[0]), "+f"(c[1]), "+f"(c[2]), "+f"(c[3])
        : "r"(a[0]), "r"(a[1]), "r"(a[2]), "r"(a[3]), "r"(b[0]), "r"(b[1]));
}

// ---------------- generic tf32 GEMM (double-buffered smem) ----------------
// C[M,N] = epilogue( sum_k A[m,k]*B[k,n] )
// AT==0: A[m,k] = A[m*lda + k]   (K contiguous)
// AT==1: A[m,k] = A[k*lda + m]   (M contiguous; used for K^T in KV)
// BT==0: B[k,n] = B[n*ldb + k]   (weights, stored [N,K])
// BT==1: B[k,n] = B[k*ldb + n]   (N contiguous)
// EPI: 0 none | 1 +bias[n] | 2 elu(+bias)+1 | 3 /z[m]
template<int AT, int BT, int EPI>
__global__ void __launch_bounds__(256)
gemm_tf32(const float* __restrict__ Ag, const float* __restrict__ Bg,
          float* __restrict__ Cg, const float* __restrict__ auxg,
          int M, int N, int K, int lda, int ldb, int ldc,
          long sA, long sB, long sC, long sAux)
{
    // 2-stage double buffer: 2 * (16*136)*4B * 2 arrays = 34.8 KB (static OK)
    __shared__ uint32_t As[2][16][136];   // ld=136 -> conflict-free frag loads
    __shared__ uint32_t Bs[2][16][136];

    const int bz = blockIdx.z;
    const float* A = Ag + (long)bz * sA;
    const float* B = Bg + (long)bz * sB;
    float*       C = Cg + (long)bz * sC;
    const float* aux = auxg + (long)bz * sAux;

    const int tid  = threadIdx.x;
    const int lane = tid & 31;
    const int warp = tid >> 5;
    const int g    = lane >> 2;   // groupID (row within mma tile)
    const int t    = lane & 3;    // threadID_in_group
    const int wm   = warp & 1;    // warp grid 2 (m) x 4 (n)
    const int wn   = warp >> 1;
    const int m0   = blockIdx.y * 128;
    const int n0   = blockIdx.x * 128;

    float acc[4][4][4];
    #pragma unroll
    for (int i = 0; i < 4; ++i)
        #pragma unroll
        for (int j = 0; j < 4; ++j)
            #pragma unroll
            for (int l = 0; l < 4; ++l) acc[i][j][l] = 0.f;

    float4 ra[2], rb[2];

    auto loadA = [&](int k0) {
        #pragma unroll
        for (int it = 0; it < 2; ++it) {
            if (AT == 0) {
                int row = (tid >> 2) + it * 64;
                int sub = tid & 3;
                ra[it] = *reinterpret_cast<const float4*>(
                    &A[(long)(m0 + row) * lda + k0 + sub * 4]);
            } else {
                int kk = (tid >> 5) + it * 8;
                int mq = tid & 31;
                ra[it] = *reinterpret_cast<const float4*>(
                    &A[(long)(k0 + kk) * lda + m0 + mq * 4]);
            }
        }
    };
    auto loadB = [&](int k0) {
        #pragma unroll
        for (int it = 0; it < 2; ++it) {
            if (BT == 0) {
                int row = (tid >> 2) + it * 64;
                int sub = tid & 3;
                rb[it] = *reinterpret_cast<const float4*>(
                    &B[(long)(n0 + row) * ldb + k0 + sub * 4]);
            } else {
                int kk = (tid >> 5) + it * 8;
                int nq = tid & 31;
                rb[it] = *reinterpret_cast<const float4*>(
                    &B[(long)(k0 + kk) * ldb + n0 + nq * 4]);
            }
        }
    };
    auto storeA = [&](int s) {
        #pragma unroll
        for (int it = 0; it < 2; ++it) {
            if (AT == 0) {
                int row = (tid >> 2) + it * 64;
                int sub = tid & 3;
                As[s][sub * 4 + 0][row] = f2tf32(ra[it].x);
                As[s][sub * 4 + 1][row] = f2tf32(ra[it].y);
                As[s][sub * 4 + 2][row] = f2tf32(ra[it].z);
                As[s][sub * 4 + 3][row] = f2tf32(ra[it].w);
            } else {
                int kk = (tid >> 5) + it * 8;
                int mq = tid & 31;
                uint4 v;
                v.x = f2tf32(ra[it].x); v.y = f2tf32(ra[it].y);
                v.z = f2tf32(ra[it].z); v.w = f2tf32(ra[it].w);
                *reinterpret_cast<uint4*>(&As[s][kk][mq * 4]) = v;
            }
        }
    };
    auto storeB = [&](int s) {
        #pragma unroll
        for (int it = 0; it < 2; ++it) {
            if (BT == 0) {
                int row = (tid >> 2) + it * 64;
                int sub = tid & 3;
                Bs[s][sub * 4 + 0][row] = f2tf32(rb[it].x);
                Bs[s][sub * 4 + 1][row] = f2tf32(rb[it].y);
                Bs[s][sub * 4 + 2][row] = f2tf32(rb[it].z);
                Bs[s][sub * 4 + 3][row] = f2tf32(rb[it].w);
            } else {
                int kk = (tid >> 5) + it * 8;
                int nq = tid & 31;
                uint4 v;
                v.x = f2tf32(rb[it].x); v.y = f2tf32(rb[it].y);
                v.z = f2tf32(rb[it].z); v.w = f2tf32(rb[it].w);
                *reinterpret_cast<uint4*>(&Bs[s][kk][nq * 4]) = v;
            }
        }
    };
    auto compute = [&](int s) {
        #pragma unroll
        for (int ks = 0; ks < 16; ks += 8) {
            uint32_t af[4][4];
            uint32_t bf[4][2];
            #pragma unroll
            for (int mt = 0; mt < 4; ++mt) {
                int mr = wm * 64 + mt * 16;
                af[mt][0] = As[s][ks + t    ][mr + g    ];
                af[mt][1] = As[s][ks + t    ][mr + g + 8];
                af[mt][2] = As[s][ks + t + 4][mr + g    ];
                af[mt][3] = As[s][ks + t + 4][mr + g + 8];
            }
            #pragma unroll
            for (int nt = 0; nt < 4; ++nt) {
                int nc = wn * 32 + nt * 8;
                bf[nt][0] = Bs[s][ks + t    ][nc + g];
                bf[nt][1] = Bs[s][ks + t + 4][nc + g];
            }
            #pragma unroll
            for (int mt = 0; mt < 4; ++mt)
                #pragma unroll
                for (int nt = 0; nt < 4; ++nt)
                    mma8(acc[mt][nt], af[mt], bf[nt]);
        }
    };

    const int KT = K / 16;
    // Prologue: fill stage 0
    loadA(0); loadB(0);
    storeA(0); storeB(0);
    __syncthreads();
    // Mainloop: ONE barrier per iteration.
    //  iter kt: prefetch kt+1 (gmem->reg), compute stage kt&1,
    //           store kt+1 into stage (kt+1)&1 (disjoint from the one being read),
    //           then barrier so next compute sees complete stores.
    for (int kt = 0; kt < KT; ++kt) {
        if (kt + 1 < KT) { loadA((kt + 1) * 16); loadB((kt + 1) * 16); }
        compute(kt & 1);
        if (kt + 1 < KT) {
            storeA((kt + 1) & 1); storeB((kt + 1) & 1);
            __syncthreads();
        }
    }

    // ---------------- epilogue ----------------
    #pragma unroll
    for (int mt = 0; mt < 4; ++mt) {
        int r0 = m0 + wm * 64 + mt * 16 + g;
        float z0 = 1.f, z1 = 1.f;
        if (EPI == 3) { z0 = aux[r0]; z1 = aux[r0 + 8]; }
        #pragma unroll
        for (int nt = 0; nt < 4; ++nt) {
            int c = n0 + wn * 32 + nt * 8 + t * 2;
            float v0 = acc[mt][nt][0], v1 = acc[mt][nt][1];
            float v2 = acc[mt][nt][2], v3 = acc[mt][nt][3];
            if (EPI == 1 || EPI == 2) {
                float b0 = aux[c], b1 = aux[c + 1];
                v0 += b0; v1 += b1; v2 += b0; v3 += b1;
            }
            if (EPI == 2) {   // elu(x)+1 : x>0 -> x+1 else exp(x)
                v0 = v0 > 0.f ? v0 + 1.f : expf(v0);
                v1 = v1 > 0.f ? v1 + 1.f : expf(v1);
                v2 = v2 > 0.f ? v2 + 1.f : expf(v2);
                v3 = v3 > 0.f ? v3 + 1.f : expf(v3);
            }
            if (EPI == 3) {
                v0 /= z0; v1 /= z0; v2 /= z1; v3 /= z1;
            }
            float2 p0 = make_float2(v0, v1);
            float2 p1 = make_float2(v2, v3);
            *reinterpret_cast<float2*>(&C[(long)r0       * ldc + c]) = p0;
            *reinterpret_cast<float2*>(&C[(long)(r0 + 8) * ldc + c]) = p1;
        }
    }
}

// ---------------- K column-sum (+1e-6) ----------------
__global__ void ksum_init() {
    int i = blockIdx.x * 256 + threadIdx.x;
    g_Ksum[i] = 1e-6f;
}

__global__ void ksum_acc() {
    int b = blockIdx.y;
    int chunk = blockIdx.x;           // 16 chunks of 256 rows
    int d4 = threadIdx.x;             // 0..255 -> float4 column group
    float4 s = make_float4(0.f, 0.f, 0.f, 0.f);
    const float* base = g_Kf + ((long)b * N_SEQ + chunk * 256) * D_DIM + d4 * 4;
    #pragma unroll 4
    for (int n = 0; n < 256; ++n) {
        float4 v = *reinterpret_cast<const float4*>(base + (long)n * D_DIM);
        s.x += v.x; s.y += v.y; s.z += v.z; s.w += v.w;
    }
    float* ks = g_Ksum + b * D_DIM + d4 * 4;
    atomicAdd(ks + 0, s.x);
    atomicAdd(ks + 1, s.y);
    atomicAdd(ks + 2, s.z);
    atomicAdd(ks + 3, s.w);
}

// ---------------- Z[b,n] = Q[b,n,:] . Ksum[b,:] ----------------
__global__ void z_kernel() {
    int warp = threadIdx.x >> 5;
    int lane = threadIdx.x & 31;
    long row = (long)blockIdx.x * 8 + warp;   // 32768 rows total
    int b = (int)(row >> 12);
    const float* q  = g_Q + row * D_DIM;
    const float* ks = g_Ksum + b * D_DIM;
    float s = 0.f;
    #pragma unroll
    for (int i = 0; i < 8; ++i) {
        int d = (lane + i * 32) * 4;
        float4 qv = *reinterpret_cast<const float4*>(&q[d]);
        float4 kv = *reinterpret_cast<const float4*>(&ks[d]);
        s += qv.x * kv.x + qv.y * kv.y + qv.z * kv.z + qv.w * kv.w;
    }
    #pragma unroll
    for (int o = 16; o > 0; o >>= 1) s += __shfl_xor_sync(0xFFFFFFFFu, s, o);
    if (lane == 0) g_Z[row] = s;
}

// ---------------- launch ----------------
extern "C" void kernel_launch(void* const* d_in, const int* in_sizes, int n_in,
                              void* d_out, int out_size)
{
    const float* x  = (const float*)d_in[0];
    const float* Wq = (const float*)d_in[1];
    const float* bq = (const float*)d_in[2];
    const float* Wk = (const float*)d_in[3];
    const float* bk = (const float*)d_in[4];
    const float* Wv = (const float*)d_in[5];
    const float* bv = (const float*)d_in[6];
    const float* Wo = (const float*)d_in[7];
    const float* bo = (const float*)d_in[8];
    float* out = (float*)d_out;

    float *pQ, *pK, *pV, *pC, *pKV, *pZ;
    cudaGetSymbolAddress((void**)&pQ,  g_Q);
    cudaGetSymbolAddress((void**)&pK,  g_Kf);
    cudaGetSymbolAddress((void**)&pV,  g_V);
    cudaGetSymbolAddress((void**)&pC,  g_Cx);
    cudaGetSymbolAddress((void**)&pKV, g_KV);
    cudaGetSymbolAddress((void**)&pZ,  g_Z);

    dim3 blk(256);
    dim3 gproj(D_DIM / 128, M_FLAT / 128, 1);        // (8, 256)

    // Q/K/V projections (elu+1 fused into Q and K)
    gemm_tf32<0,0,2><<<gproj, blk>>>(x, Wq, pQ, bq,
        M_FLAT, D_DIM, D_DIM, D_DIM, D_DIM, D_DIM, 0, 0, 0, 0);
    gemm_tf32<0,0,2><<<gproj, blk>>>(x, Wk, pK, bk,
        M_FLAT, D_DIM, D_DIM, D_DIM, D_DIM, D_DIM, 0, 0, 0, 0);
    gemm_tf32<0,0,1><<<gproj, blk>>>(x, Wv, pV, bv,
        M_FLAT, D_DIM, D_DIM, D_DIM, D_DIM, D_DIM, 0, 0, 0, 0);

    // Ksum (+eps) and Z
    ksum_init<<<(N_BATCH * D_DIM) / 256, 256>>>();
    ksum_acc<<<dim3(16, N_BATCH), 256>>>();
    z_kernel<<<M_FLAT / 8, 256>>>();

    // KV[b] = K[b]^T @ V[b]   (M=D, N=D, K=seq)
    gemm_tf32<1,1,0><<<dim3(8, 8, N_BATCH), blk>>>(pK, pV, pKV, pZ,
        D_DIM, D_DIM, N_SEQ, D_DIM, D_DIM, D_DIM,
        (long)N_SEQ * D_DIM, (long)N_SEQ * D_DIM, (long)D_DIM * D_DIM, 0);

    // context[b] = (Q[b] @ KV[b]) / Z[b]
    gemm_tf32<0,1,3><<<dim3(8, 32, N_BATCH), blk>>>(pQ, pKV, pC, pZ,
        N_SEQ, D_DIM, D_DIM, D_DIM, D_DIM, D_DIM,
        (long)N_SEQ * D_DIM, (long)D_DIM * D_DIM, (long)N_SEQ * D_DIM, N_SEQ);

    // out = context @ Wo^T + bo
    gemm_tf32<0,0,1><<<gproj, blk>>>(pC, Wo, out, bo,
        M_FLAT, D_DIM, D_DIM, D_DIM, D_DIM, D_DIM, 0, 0, 0, 0);
}